// round 9
// baseline (speedup 1.0000x reference)
#include <cuda_runtime.h>

// ---------------------------------------------------------------------------
// SimpleRNN: 2-layer bidirectional tanh RNN + FC head.  B=32,T=2048,H=512.
//  - recurrence: Whh register-resident (128 regs/thread), fma.f32x2 along k,
//    ONE phase per timestep (4 batches together), h broadcast via 8 x 1KB
//    cp.async.bulk cluster copies + mbarrier complete_tx.
//  - GEMMs: R3 version (BM128/BN64/BK16, f32x2 packed along M).
// ---------------------------------------------------------------------------

#define B_   32
#define T_   2048
#define H_   512
#define V_   8192
#define BT_  (B_ * T_)     // 65536
#define NW_  1024          // 2*H

__device__ float g_WihT[2 * V_ * H_];     //  33.5 MB
__device__ float g_pre [67108864];        // 268 MB  [BT][1024]
__device__ float g_hcat[67108864];        // 268 MB  [BT][1024]

// ---------------------------------------------------------------------------
// 1) Transpose Wih0 [2][H][V] -> g_WihT [2][V][H]
// ---------------------------------------------------------------------------
__global__ void transpose_k(const float* __restrict__ Wih0)
{
    __shared__ float tile[32][33];
    int d  = blockIdx.z;
    const float* S = Wih0   + (size_t)d * H_ * V_;
    float*       D = g_WihT + (size_t)d * V_ * H_;
    int v0 = blockIdx.x * 32;
    int h0 = blockIdx.y * 32;
    int tx = threadIdx.x, ty = threadIdx.y;
#pragma unroll
    for (int i = 0; i < 4; i++)
        tile[ty + 8 * i][tx] = S[(size_t)(h0 + ty + 8 * i) * V_ + v0 + tx];
    __syncthreads();
#pragma unroll
    for (int i = 0; i < 4; i++)
        D[(size_t)(v0 + ty + 8 * i) * H_ + h0 + tx] = tile[tx][ty + 8 * i];
}

// ---------------------------------------------------------------------------
// 2) Gather + biases -> g_pre
// ---------------------------------------------------------------------------
__global__ void gather_k(const int* __restrict__ x,
                         const float* __restrict__ bih0,
                         const float* __restrict__ bhh0)
{
    int bt  = blockIdx.x;
    int idx = __ldg(&x[bt]);
    int o   = threadIdx.x * 4;
    int dir = o >> 9;
    int h   = o & 511;
    float4 w  = *(const float4*)&g_WihT[((size_t)dir * V_ + idx) * H_ + h];
    float4 b1 = *(const float4*)&bih0[o];
    float4 b2 = *(const float4*)&bhh0[o];
    float4 r;
    r.x = w.x + b1.x + b2.x;
    r.y = w.y + b1.y + b2.y;
    r.z = w.z + b1.z + b2.z;
    r.w = w.w + b1.w + b2.w;
    *(float4*)&g_pre[(size_t)bt * NW_ + o] = r;
}

// ---------------------------------------------------------------------------
// 3/5) Recurrence. 16 clusters x 8 CTAs. CTA rank owns 64 Whh rows in REGS.
// ONE phase per timestep: thread (kq=tid&3, r=tid>>2) holds w[grow][kq*128..+128)
// in 64 u64 regs, computes 4 batch partial dots (4 chains), quad shuffle-
// reduce, lane kq keeps batch kq, stages 256 floats, tid0 bulk-copies 1KB to
// all 8 peers' next h-buffer (count-1 mbarrier, expect_tx = 8*1024).
// h-buffer per buf: [owner 0..7][260] ; owner block = [batch 0..3][64 rows].
// ---------------------------------------------------------------------------
#define FMA2(d, a, b) \
    asm("fma.rn.f32x2 %0, %1, %2, %0;" : "+l"(d) : "l"(a), "l"(b))

__global__ void __cluster_dims__(8, 1, 1) __launch_bounds__(256, 1)
rnn_layer_k(const float* __restrict__ Whh)
{
    __shared__ __align__(16) float s_h[2][8 * 260];         // 16.6 KB
    __shared__ __align__(16) float s_stage[2][256];         // 2 KB
    __shared__ __align__(8)  unsigned long long s_mbar[2];

    int tid  = threadIdx.x;
    int rank = blockIdx.x & 7;
    int cid  = blockIdx.x >> 3;
    int dir  = cid >> 3;
    int b0   = (cid & 7) * 4;

    int kq   = tid & 3;                  // k-quarter / batch lane
    int r    = tid >> 2;                 // 0..63
    int grow = rank * 64 + r;
    int colbase = dir * H_ + grow;

    // --- my 128-float Whh chunk in registers (64 packed u64) ---
    unsigned long long wp[64];
    const unsigned long long* Wrow = (const unsigned long long*)
        (Whh + ((size_t)dir * H_ + grow) * H_ + kq * 128);
#pragma unroll
    for (int i = 0; i < 64; i++) wp[i] = Wrow[i];

    // --- zero h buffers, init barriers, arm prologue expects ---
    for (int i = tid; i < 2 * 8 * 260; i += 256) ((float*)s_h)[i] = 0.0f;
    unsigned int hbase = (unsigned int)__cvta_generic_to_shared(&s_h[0][0]);
    unsigned int sbase = (unsigned int)__cvta_generic_to_shared(&s_stage[0][0]);
    unsigned int mbase = (unsigned int)__cvta_generic_to_shared(&s_mbar[0]);
    if (tid == 0) {
#pragma unroll
        for (int i = 0; i < 2; i++) {
            asm volatile("mbarrier.init.shared.b64 [%0], %1;"
                         :: "r"(mbase + i * 8), "r"(1) : "memory");
            asm volatile("mbarrier.arrive.expect_tx.shared.b64 _, [%0], %1;"
                         :: "r"(mbase + i * 8), "r"(8192) : "memory");
        }
    }
    __syncthreads();
    asm volatile("barrier.cluster.arrive.aligned;" ::: "memory");
    asm volatile("barrier.cluster.wait.aligned;" ::: "memory");

    unsigned int peer[8];
    unsigned int mdelta = mbase - hbase;
#pragma unroll
    for (int p = 0; p < 8; p++)
        asm volatile("mapa.shared::cluster.u32 %0, %1, %2;"
                     : "=r"(peer[p]) : "r"(hbase), "r"(p));

    size_t batch = (size_t)(b0 + kq);
    float pv = __ldg(&g_pre[((batch * T_ + (dir ? (T_ - 1) : 0)) << 10) + colbase]);

    for (int t = 0; t < T_; t++) {
        int b = t & 1;
        unsigned int mb = mbase + (unsigned)(b * 8);

        // 1) wait for this buffer (t=0 reads zero-init, no wait)
        if (t > 0) {
            unsigned int par = (unsigned)(((t - 1) >> 1) & 1);
            unsigned int done;
            asm volatile(
                "{\n\t.reg .pred p;\n\t"
                "mbarrier.try_wait.parity.acquire.cta.shared::cta.b64 p, [%1], %2;\n\t"
                "selp.b32 %0, 1, 0, p;\n\t}"
                : "=r"(done) : "r"(mb), "r"(par) : "memory");
            if (!done) {
                asm volatile(
                    "{\n\t.reg .pred P1;\n\t"
                    "WL_%=:\n\t"
                    "mbarrier.try_wait.parity.acquire.cta.shared::cta.b64 P1, [%0], %1, 0x989680;\n\t"
                    "@P1 bra.uni WD_%=;\n\t"
                    "bra.uni WL_%=;\n\t"
                    "WD_%=:\n\t}"
                    :: "r"(mb), "r"(par) : "memory");
            }
        }
        // 2) re-arm this barrier for its use at t+2
        if (tid == 0 && t >= 1 && t + 2 <= T_ - 1)
            asm volatile("mbarrier.arrive.expect_tx.shared.b64 _, [%0], %1;"
                         :: "r"(mb), "r"(8192) : "memory");

        // 3) partial dots: 4 batch chains; owners 2kq, 2kq+1
        const ulonglong2* hp = (const ulonglong2*)&s_h[b][0];
        unsigned long long a0 = 0ULL, a1 = 0ULL, a2 = 0ULL, a3 = 0ULL;
#pragma unroll
        for (int o = 0; o < 2; o++) {
            int ob = (2 * kq + o) * 65;        // owner block in 16B units
#pragma unroll
            for (int j = 0; j < 16; j++) {
                ulonglong2 h0 = hp[ob + j];
                ulonglong2 h1 = hp[ob + 16 + j];
                ulonglong2 h2 = hp[ob + 32 + j];
                ulonglong2 h3 = hp[ob + 48 + j];
                int wi = o * 32 + 2 * j;
                FMA2(a0, wp[wi], h0.x); FMA2(a0, wp[wi + 1], h0.y);
                FMA2(a1, wp[wi], h1.x); FMA2(a1, wp[wi + 1], h1.y);
                FMA2(a2, wp[wi], h2.x); FMA2(a2, wp[wi + 1], h2.y);
                FMA2(a3, wp[wi], h3.x); FMA2(a3, wp[wi + 1], h3.y);
            }
        }
        float s0, s1, s2, s3;
        {
            float lo, hi;
            asm("mov.b64 {%0, %1}, %2;" : "=f"(lo), "=f"(hi) : "l"(a0)); s0 = lo + hi;
            asm("mov.b64 {%0, %1}, %2;" : "=f"(lo), "=f"(hi) : "l"(a1)); s1 = lo + hi;
            asm("mov.b64 {%0, %1}, %2;" : "=f"(lo), "=f"(hi) : "l"(a2)); s2 = lo + hi;
            asm("mov.b64 {%0, %1}, %2;" : "=f"(lo), "=f"(hi) : "l"(a3)); s3 = lo + hi;
        }
        s0 += __shfl_xor_sync(0xffffffffu, s0, 1);
        s1 += __shfl_xor_sync(0xffffffffu, s1, 1);
        s2 += __shfl_xor_sync(0xffffffffu, s2, 1);
        s3 += __shfl_xor_sync(0xffffffffu, s3, 1);
        s0 += __shfl_xor_sync(0xffffffffu, s0, 2);
        s1 += __shfl_xor_sync(0xffffffffu, s1, 2);
        s2 += __shfl_xor_sync(0xffffffffu, s2, 2);
        s3 += __shfl_xor_sync(0xffffffffu, s3, 2);
        float sel = (kq & 2) ? ((kq & 1) ? s3 : s2) : ((kq & 1) ? s1 : s0);
        float hn  = tanhf(pv + sel);

        // 4) global store + staging + pv prefetch
        int tt = dir ? (T_ - 1 - t) : t;
        g_hcat[((batch * T_ + tt) << 10) + colbase] = hn;
        s_stage[b][kq * 64 + r] = hn;
        if (t < T_ - 1) {
            int tn = dir ? (T_ - 2 - t) : (t + 1);
            pv = __ldg(&g_pre[((batch * T_ + tn) << 10) + colbase]);
        }

        // 5) staging visible + all reads of buf b complete
        __syncthreads();

        // 6) broadcast my 1KB block to all 8 CTAs' buf b^1
        if (tid == 0 && t < T_ - 1) {
            asm volatile("fence.proxy.async;" ::: "memory");
            unsigned int src  = sbase + (unsigned)(b * 1024);
            unsigned int doff = (unsigned)(((b ^ 1) * 8 * 260 + rank * 260) * 4);
            unsigned int moff = mdelta + (unsigned)((b ^ 1) * 8);
#pragma unroll
            for (int p = 0; p < 8; p++) {
                asm volatile(
                    "cp.async.bulk.shared::cluster.shared::cta.mbarrier::complete_tx::bytes "
                    "[%0], [%1], %2, [%3];"
                    :: "r"(peer[p] + doff), "r"(src), "r"(1024),
                       "r"(peer[p] + moff) : "memory");
            }
        }
    }
    asm volatile("barrier.cluster.arrive.aligned;" ::: "memory");
    asm volatile("barrier.cluster.wait.aligned;" ::: "memory");
}

// ---------------------------------------------------------------------------
// 4/6) C[m][n] = sum_k g_hcat[m][k] * Bw[n][k] + bias1[n] (+ bias2[n])
// M=65536, N=1024, K=1024. BM=128, BN=64, BK=16, 256 thr, 8x4 microtile,
// f32x2 packed along M.  (R3 measured-best version.)
// ---------------------------------------------------------------------------
__global__ __launch_bounds__(256)
void gemm_k(const float* __restrict__ Bw,
            const float* __restrict__ bias1,
            const float* __restrict__ bias2,
            float* __restrict__ Cext,
            int use_pre)
{
    __shared__ float As[16 * 130];   // [k][m]
    __shared__ float Bs[16 * 68];    // [k][n]

    float* C = use_pre ? g_pre : Cext;
    const int K = 1024;
    int m0 = blockIdx.y * 128;
    int n0 = blockIdx.x * 64;
    int tid = threadIdx.x;
    int tx = tid & 15;               // n-group: cols n0 + tx*4 .. +4
    int ty = tid >> 4;               // m-group: rows m0 + ty*8 .. +8

    unsigned long long acc[4][4];    // [m-pair][n] packed f32x2
#pragma unroll
    for (int i = 0; i < 4; i++)
#pragma unroll
        for (int j = 0; j < 4; j++) acc[i][j] = 0ULL;

    for (int kt = 0; kt < K; kt += 16) {
#pragma unroll
        for (int i = 0; i < 2; i++) {
            int j  = tid + 256 * i;
            int m  = j >> 2, kq = j & 3;
            float4 v = *(const float4*)&g_hcat[(size_t)(m0 + m) * 1024 + kt + kq * 4];
            As[(kq * 4 + 0) * 130 + m] = v.x;
            As[(kq * 4 + 1) * 130 + m] = v.y;
            As[(kq * 4 + 2) * 130 + m] = v.z;
            As[(kq * 4 + 3) * 130 + m] = v.w;
        }
        {
            int n = tid >> 2, kq = tid & 3;
            float4 v = *(const float4*)&Bw[(size_t)(n0 + n) * 1024 + kt + kq * 4];
            Bs[(kq * 4 + 0) * 68 + n] = v.x;
            Bs[(kq * 4 + 1) * 68 + n] = v.y;
            Bs[(kq * 4 + 2) * 68 + n] = v.z;
            Bs[(kq * 4 + 3) * 68 + n] = v.w;
        }
        __syncthreads();

#pragma unroll
        for (int k = 0; k < 16; k++) {
            const unsigned long long* ap =
                (const unsigned long long*)(As + k * 130 + ty * 8);
            unsigned long long a[4];
            a[0] = ap[0]; a[1] = ap[1]; a[2] = ap[2]; a[3] = ap[3];
            float4 bv = *(const float4*)(Bs + k * 68 + tx * 4);
            unsigned long long b[4];
            asm("mov.b64 %0, {%1, %1};" : "=l"(b[0]) : "f"(bv.x));
            asm("mov.b64 %0, {%1, %1};" : "=l"(b[1]) : "f"(bv.y));
            asm("mov.b64 %0, {%1, %1};" : "=l"(b[2]) : "f"(bv.z));
            asm("mov.b64 %0, {%1, %1};" : "=l"(b[3]) : "f"(bv.w));
#pragma unroll
            for (int i = 0; i < 4; i++)
#pragma unroll
                for (int j = 0; j < 4; j++)
                    FMA2(acc[i][j], a[i], b[j]);
        }
        __syncthreads();
    }

    float bs[4];
#pragma unroll
    for (int j = 0; j < 4; j++) {
        int n = n0 + tx * 4 + j;
        bs[j] = bias1[n] + (bias2 ? bias2[n] : 0.0f);
    }
#pragma unroll
    for (int i = 0; i < 4; i++) {
        float lo[4], hi[4];
#pragma unroll
        for (int j = 0; j < 4; j++) {
            float l, h;
            asm("mov.b64 {%0, %1}, %2;" : "=f"(l), "=f"(h) : "l"(acc[i][j]));
            lo[j] = l; hi[j] = h;
        }
        int mA = m0 + ty * 8 + 2 * i;
        float4 r0, r1;
        r0.x = lo[0] + bs[0]; r0.y = lo[1] + bs[1];
        r0.z = lo[2] + bs[2]; r0.w = lo[3] + bs[3];
        r1.x = hi[0] + bs[0]; r1.y = hi[1] + bs[1];
        r1.z = hi[2] + bs[2]; r1.w = hi[3] + bs[3];
        *(float4*)&C[(size_t)mA * 1024 + n0 + tx * 4]       = r0;
        *(float4*)&C[(size_t)(mA + 1) * 1024 + n0 + tx * 4] = r1;
    }
}

// ---------------------------------------------------------------------------
extern "C" void kernel_launch(void* const* d_in, const int* in_sizes, int n_in,
                              void* d_out, int out_size)
{
    const int*   x    = (const int*)  d_in[0];
    const float* Wih0 = (const float*)d_in[1];
    const float* Whh0 = (const float*)d_in[2];
    const float* bih0 = (const float*)d_in[3];
    const float* bhh0 = (const float*)d_in[4];
    const float* Wih1 = (const float*)d_in[5];
    const float* Whh1 = (const float*)d_in[6];
    const float* bih1 = (const float*)d_in[7];
    const float* bhh1 = (const float*)d_in[8];
    const float* fcW  = (const float*)d_in[9];
    const float* fcb  = (const float*)d_in[10];
    float* out = (float*)d_out;

    transpose_k<<<dim3(V_ / 32, H_ / 32, 2), dim3(32, 8)>>>(Wih0);
    gather_k<<<BT_, 256>>>(x, bih0, bhh0);
    rnn_layer_k<<<128, 256>>>(Whh0);
    gemm_k<<<dim3(16, BT_ / 128), 256>>>(Wih1, bih1, bhh1, nullptr, 1);
    rnn_layer_k<<<128, 256>>>(Whh1);
    gemm_k<<<dim3(16, BT_ / 128), 256>>>(fcW, fcb, nullptr, out, 0);
}

// round 10
// speedup vs baseline: 1.2031x; 1.2031x over previous
#include <cuda_runtime.h>

// ---------------------------------------------------------------------------
// SimpleRNN: 2-layer bidirectional tanh RNN + FC head.  B=32,T=2048,H=512.
//  - recurrence: Whh register-resident, fma.f32x2; h broadcast across 8-CTA
//    cluster via cp.async.bulk (512B per group) + mbarrier complete_tx;
//    2 batch-pair pipelines; busy test_wait polling (no HW sleep);
//    bulk copies issued by 8 lanes in parallel.
//  - GEMMs: R3 measured-best (BM128/BN64/BK16, f32x2 packed along M).
// ---------------------------------------------------------------------------

#define B_   32
#define T_   2048
#define H_   512
#define V_   8192
#define BT_  (B_ * T_)     // 65536
#define NW_  1024          // 2*H

__device__ float g_WihT[2 * V_ * H_];     //  33.5 MB
__device__ float g_pre [67108864];        // 268 MB  [BT][1024]
__device__ float g_hcat[67108864];        // 268 MB  [BT][1024]

// ---------------------------------------------------------------------------
// 1) Transpose Wih0 [2][H][V] -> g_WihT [2][V][H]
// ---------------------------------------------------------------------------
__global__ void transpose_k(const float* __restrict__ Wih0)
{
    __shared__ float tile[32][33];
    int d  = blockIdx.z;
    const float* S = Wih0   + (size_t)d * H_ * V_;
    float*       D = g_WihT + (size_t)d * V_ * H_;
    int v0 = blockIdx.x * 32;
    int h0 = blockIdx.y * 32;
    int tx = threadIdx.x, ty = threadIdx.y;
#pragma unroll
    for (int i = 0; i < 4; i++)
        tile[ty + 8 * i][tx] = S[(size_t)(h0 + ty + 8 * i) * V_ + v0 + tx];
    __syncthreads();
#pragma unroll
    for (int i = 0; i < 4; i++)
        D[(size_t)(v0 + ty + 8 * i) * H_ + h0 + tx] = tile[tx][ty + 8 * i];
}

// ---------------------------------------------------------------------------
// 2) Gather + biases -> g_pre
// ---------------------------------------------------------------------------
__global__ void gather_k(const int* __restrict__ x,
                         const float* __restrict__ bih0,
                         const float* __restrict__ bhh0)
{
    int bt  = blockIdx.x;
    int idx = __ldg(&x[bt]);
    int o   = threadIdx.x * 4;
    int dir = o >> 9;
    int h   = o & 511;
    float4 w  = *(const float4*)&g_WihT[((size_t)dir * V_ + idx) * H_ + h];
    float4 b1 = *(const float4*)&bih0[o];
    float4 b2 = *(const float4*)&bhh0[o];
    float4 r;
    r.x = w.x + b1.x + b2.x;
    r.y = w.y + b1.y + b2.y;
    r.z = w.z + b1.z + b2.z;
    r.w = w.w + b1.w + b2.w;
    *(float4*)&g_pre[(size_t)bt * NW_ + o] = r;
}

// ---------------------------------------------------------------------------
// dummy: shifts rnn_layer_k to overall profiled ordinal (harness prepends 2)
// ---------------------------------------------------------------------------
__global__ void dummy_k() {}

// ---------------------------------------------------------------------------
// 3/5) Recurrence. 16 clusters x 8 CTAs. CTA rank owns 64 Whh rows in REGS.
// Two batch-pair groups g={0,1}, double-buffered h, count-1 mbarriers with
// expect_tx=4096 per phase. Broadcast: stage 128 floats, lanes 0-7 each send
// one 512B cp.async.bulk to peer[lane]'s next buffer. Busy test_wait polling.
// ---------------------------------------------------------------------------
#define FMA2(d, a, b) \
    asm("fma.rn.f32x2 %0, %1, %2, %0;" : "+l"(d) : "l"(a), "l"(b))

__global__ void __cluster_dims__(8, 1, 1) __launch_bounds__(256, 1)
rnn_layer_k(const float* __restrict__ Whh)
{
    __shared__ __align__(16) float s_h[2][2][1056];         // [g][buf][8*132]
    __shared__ __align__(16) float s_stage[2][2][128];      // [g][buf][2*64]
    __shared__ __align__(8)  unsigned long long s_mbar[4];  // [g*2+buf]

    int tid  = threadIdx.x;
    int rank = blockIdx.x & 7;
    int cid  = blockIdx.x >> 3;
    int dir  = cid >> 3;
    int b0   = (cid & 7) * 4;

    int kq   = tid & 3;                  // quad lane
    int r    = tid >> 2;                 // 0..63
    int grow = rank * 64 + r;
    int colbase = dir * H_ + grow;

    // --- my 128-float Whh chunk in registers (64 packed u64) ---
    unsigned long long wp[64];
    const unsigned long long* Wrow = (const unsigned long long*)
        (Whh + ((size_t)dir * H_ + grow) * H_ + kq * 128);
#pragma unroll
    for (int i = 0; i < 64; i++) wp[i] = Wrow[i];

    // --- zero h buffers, init barriers, arm prologue expects ---
    for (int i = tid; i < 2 * 2 * 1056; i += 256) ((float*)s_h)[i] = 0.0f;
    unsigned int hbase = (unsigned int)__cvta_generic_to_shared(&s_h[0][0][0]);
    unsigned int sbase = (unsigned int)__cvta_generic_to_shared(&s_stage[0][0][0]);
    unsigned int mbase = (unsigned int)__cvta_generic_to_shared(&s_mbar[0]);
    if (tid == 0) {
#pragma unroll
        for (int i = 0; i < 4; i++) {
            asm volatile("mbarrier.init.shared.b64 [%0], %1;"
                         :: "r"(mbase + i * 8), "r"(1) : "memory");
            asm volatile("mbarrier.arrive.expect_tx.shared.b64 _, [%0], %1;"
                         :: "r"(mbase + i * 8), "r"(4096) : "memory");
        }
    }
    __syncthreads();
    asm volatile("barrier.cluster.arrive.aligned;" ::: "memory");
    asm volatile("barrier.cluster.wait.aligned;" ::: "memory");

    unsigned int peer[8];
    unsigned int mdelta = mbase - hbase;
#pragma unroll
    for (int p = 0; p < 8; p++)
        asm volatile("mapa.shared::cluster.u32 %0, %1, %2;"
                     : "=r"(peer[p]) : "r"(hbase), "r"(p));
    unsigned int mypeer = peer[tid & 7];

    // pv prefetch (lanes kq<2 own batch b0+2g+kq)
    float pv[2] = {0.0f, 0.0f};
    if (kq < 2) {
#pragma unroll
        for (int g = 0; g < 2; g++)
            pv[g] = __ldg(&g_pre[(((size_t)(b0 + 2 * g + kq) * T_ +
                                   (dir ? (T_ - 1) : 0)) << 10) + colbase]);
    }

    for (int t = 0; t < T_; t++) {
        int b = t & 1;
        unsigned int par = (unsigned)((((t + 1) >> 1) - 1) & 1);
#pragma unroll
        for (int g = 0; g < 2; g++) {
            unsigned int mb = mbase + (unsigned)((g * 2 + b) * 8);

            // 1) busy-poll for this buffer's data (t=0 reads zero-init)
            if (t > 0) {
                unsigned int done = 0;
                do {
                    asm volatile(
                        "{\n\t.reg .pred p;\n\t"
                        "mbarrier.test_wait.parity.acquire.cta.shared::cta.b64 p, [%1], %2;\n\t"
                        "selp.b32 %0, 1, 0, p;\n\t}"
                        : "=r"(done) : "r"(mb), "r"(par) : "memory");
                } while (!done);
            }
            // 2) re-arm this barrier for its next use (t+2)
            if (tid == 0 && t >= 1 && t + 2 <= T_ - 1)
                asm volatile("mbarrier.arrive.expect_tx.shared.b64 _, [%0], %1;"
                             :: "r"(mb), "r"(4096) : "memory");

            // 3) partial dots: owners 2kq, 2kq+1; both batches of this group
            const ulonglong2* hp = (const ulonglong2*)&s_h[g][b][0];
            unsigned long long a0 = 0ULL, a1 = 0ULL;
#pragma unroll
            for (int o = 0; o < 2; o++) {
                int ob = (2 * kq + o) * 33;      // owner block, 16B units
#pragma unroll
                for (int j = 0; j < 16; j++) {
                    ulonglong2 h0 = hp[ob + j];       // batch-local 0
                    ulonglong2 h1 = hp[ob + 16 + j];  // batch-local 1
                    int wi = o * 32 + 2 * j;
                    FMA2(a0, wp[wi], h0.x); FMA2(a0, wp[wi + 1], h0.y);
                    FMA2(a1, wp[wi], h1.x); FMA2(a1, wp[wi + 1], h1.y);
                }
            }
            float s0, s1;
            {
                float lo, hi;
                asm("mov.b64 {%0, %1}, %2;" : "=f"(lo), "=f"(hi) : "l"(a0)); s0 = lo + hi;
                asm("mov.b64 {%0, %1}, %2;" : "=f"(lo), "=f"(hi) : "l"(a1)); s1 = lo + hi;
            }
            s0 += __shfl_xor_sync(0xffffffffu, s0, 1);
            s1 += __shfl_xor_sync(0xffffffffu, s1, 1);
            s0 += __shfl_xor_sync(0xffffffffu, s0, 2);
            s1 += __shfl_xor_sync(0xffffffffu, s1, 2);
            float sel = (kq & 1) ? s1 : s0;
            float hn  = tanhf(pv[g] + sel);

            // 4) global store + staging + pv prefetch (lanes kq<2 own a batch)
            if (kq < 2) {
                int tt = dir ? (T_ - 1 - t) : t;
                size_t batch = (size_t)(b0 + 2 * g + kq);
                g_hcat[((batch * T_ + tt) << 10) + colbase] = hn;
                s_stage[g][b][kq * 64 + r] = hn;
                if (t < T_ - 1) {
                    int tn = dir ? (T_ - 2 - t) : (t + 1);
                    pv[g] = __ldg(&g_pre[((batch * T_ + tn) << 10) + colbase]);
                }
            }

            // 5) staging visible + all reads of buf b complete
            __syncthreads();

            // 6) broadcast: lanes 0-7 each send one 512B block to peer[lane]
            if (tid < 8 && t < T_ - 1) {
                asm volatile("fence.proxy.async.shared::cta;" ::: "memory");
                unsigned int src  = sbase + (unsigned)((g * 2 + b) * 512);
                unsigned int doff = (unsigned)(((g * 2 + (b ^ 1)) * 1056 + rank * 132) * 4);
                unsigned int moff = mdelta + (unsigned)((g * 2 + (b ^ 1)) * 8);
                asm volatile(
                    "cp.async.bulk.shared::cluster.shared::cta.mbarrier::complete_tx::bytes "
                    "[%0], [%1], %2, [%3];"
                    :: "r"(mypeer + doff), "r"(src), "r"(512),
                       "r"(mypeer + moff) : "memory");
            }
        }
    }
    asm volatile("barrier.cluster.arrive.aligned;" ::: "memory");
    asm volatile("barrier.cluster.wait.aligned;" ::: "memory");
}

// ---------------------------------------------------------------------------
// 4/6) C[m][n] = sum_k g_hcat[m][k] * Bw[n][k] + bias1[n] (+ bias2[n])
// M=65536, N=1024, K=1024. BM=128, BN=64, BK=16, 256 thr, 8x4 microtile,
// f32x2 packed along M.  (R3 measured-best version, verbatim.)
// ---------------------------------------------------------------------------
__global__ __launch_bounds__(256)
void gemm_k(const float* __restrict__ Bw,
            const float* __restrict__ bias1,
            const float* __restrict__ bias2,
            float* __restrict__ Cext,
            int use_pre)
{
    __shared__ float As[16 * 130];   // [k][m]
    __shared__ float Bs[16 * 68];    // [k][n]

    float* C = use_pre ? g_pre : Cext;
    const int K = 1024;
    int m0 = blockIdx.y * 128;
    int n0 = blockIdx.x * 64;
    int tid = threadIdx.x;
    int tx = tid & 15;               // n-group: cols n0 + tx*4 .. +4
    int ty = tid >> 4;               // m-group: rows m0 + ty*8 .. +8

    unsigned long long acc[4][4];    // [m-pair][n] packed f32x2
#pragma unroll
    for (int i = 0; i < 4; i++)
#pragma unroll
        for (int j = 0; j < 4; j++) acc[i][j] = 0ULL;

    for (int kt = 0; kt < K; kt += 16) {
#pragma unroll
        for (int i = 0; i < 2; i++) {
            int j  = tid + 256 * i;
            int m  = j >> 2, kq = j & 3;
            float4 v = *(const float4*)&g_hcat[(size_t)(m0 + m) * 1024 + kt + kq * 4];
            As[(kq * 4 + 0) * 130 + m] = v.x;
            As[(kq * 4 + 1) * 130 + m] = v.y;
            As[(kq * 4 + 2) * 130 + m] = v.z;
            As[(kq * 4 + 3) * 130 + m] = v.w;
        }
        {
            int n = tid >> 2, kq = tid & 3;
            float4 v = *(const float4*)&Bw[(size_t)(n0 + n) * 1024 + kt + kq * 4];
            Bs[(kq * 4 + 0) * 68 + n] = v.x;
            Bs[(kq * 4 + 1) * 68 + n] = v.y;
            Bs[(kq * 4 + 2) * 68 + n] = v.z;
            Bs[(kq * 4 + 3) * 68 + n] = v.w;
        }
        __syncthreads();

#pragma unroll
        for (int k = 0; k < 16; k++) {
            const unsigned long long* ap =
                (const unsigned long long*)(As + k * 130 + ty * 8);
            unsigned long long a[4];
            a[0] = ap[0]; a[1] = ap[1]; a[2] = ap[2]; a[3] = ap[3];
            float4 bv = *(const float4*)(Bs + k * 68 + tx * 4);
            unsigned long long b[4];
            asm("mov.b64 %0, {%1, %1};" : "=l"(b[0]) : "f"(bv.x));
            asm("mov.b64 %0, {%1, %1};" : "=l"(b[1]) : "f"(bv.y));
            asm("mov.b64 %0, {%1, %1};" : "=l"(b[2]) : "f"(bv.z));
            asm("mov.b64 %0, {%1, %1};" : "=l"(b[3]) : "f"(bv.w));
#pragma unroll
            for (int i = 0; i < 4; i++)
#pragma unroll
                for (int j = 0; j < 4; j++)
                    FMA2(acc[i][j], a[i], b[j]);
        }
        __syncthreads();
    }

    float bs[4];
#pragma unroll
    for (int j = 0; j < 4; j++) {
        int n = n0 + tx * 4 + j;
        bs[j] = bias1[n] + (bias2 ? bias2[n] : 0.0f);
    }
#pragma unroll
    for (int i = 0; i < 4; i++) {
        float lo[4], hi[4];
#pragma unroll
        for (int j = 0; j < 4; j++) {
            float l, h;
            asm("mov.b64 {%0, %1}, %2;" : "=f"(l), "=f"(h) : "l"(acc[i][j]));
            lo[j] = l; hi[j] = h;
        }
        int mA = m0 + ty * 8 + 2 * i;
        float4 r0, r1;
        r0.x = lo[0] + bs[0]; r0.y = lo[1] + bs[1];
        r0.z = lo[2] + bs[2]; r0.w = lo[3] + bs[3];
        r1.x = hi[0] + bs[0]; r1.y = hi[1] + bs[1];
        r1.z = hi[2] + bs[2]; r1.w = hi[3] + bs[3];
        *(float4*)&C[(size_t)mA * 1024 + n0 + tx * 4]       = r0;
        *(float4*)&C[(size_t)(mA + 1) * 1024 + n0 + tx * 4] = r1;
    }
}

// ---------------------------------------------------------------------------
extern "C" void kernel_launch(void* const* d_in, const int* in_sizes, int n_in,
                              void* d_out, int out_size)
{
    const int*   x    = (const int*)  d_in[0];
    const float* Wih0 = (const float*)d_in[1];
    const float* Whh0 = (const float*)d_in[2];
    const float* bih0 = (const float*)d_in[3];
    const float* bhh0 = (const float*)d_in[4];
    const float* Wih1 = (const float*)d_in[5];
    const float* Whh1 = (const float*)d_in[6];
    const float* bih1 = (const float*)d_in[7];
    const float* bhh1 = (const float*)d_in[8];
    const float* fcW  = (const float*)d_in[9];
    const float* fcb  = (const float*)d_in[10];
    float* out = (float*)d_out;

    transpose_k<<<dim3(V_ / 32, H_ / 32, 2), dim3(32, 8)>>>(Wih0);      // my #1
    gather_k<<<BT_, 256>>>(x, bih0, bhh0);                              // my #2
    dummy_k<<<1, 32>>>();                                               // my #3
    rnn_layer_k<<<128, 256>>>(Whh0);                                    // my #4 <- ncu
    gemm_k<<<dim3(16, BT_ / 128), 256>>>(Wih1, bih1, bhh1, nullptr, 1); // my #5
    rnn_layer_k<<<128, 256>>>(Whh1);                                    // my #6
    gemm_k<<<dim3(16, BT_ / 128), 256>>>(fcW, fcb, nullptr, out, 0);    // my #7
}